// round 6
// baseline (speedup 1.0000x reference)
#include <cuda_runtime.h>
#include <cuda_bf16.h>
#include <mma.h>

using namespace nvcuda;

#define Nn 100000
#define Rr 6
#define Ee 400000
#define Ff 128
#define RE (Rr*Ee)        // 2,400,000 edges total
#define NR (Nn*Rr)        // 600,000 (dst,rel) rows
#define SCAN_BLKS 586     // ceil(NR/1024)
#define MBLK 128
#define NBLKS ((Nn + MBLK - 1) / MBLK)   // 782

// ---------------- scratch (__device__ globals; no runtime alloc) -------------
__device__ int   g_cntout[NR];                 // out-degree per (r,src)
__device__ int   g_counts[NR];                 // CSR row counts, row = dst*Rr+r (== in-degree)
__device__ float g_ns[NR];                     // norm_src per (r,n)
__device__ float g_nd[NR];                     // norm_dst per (r,n)
__device__ int   g_off[NR];                    // CSR row offsets (exclusive)
__device__ int   g_cursor[NR];                 // scatter cursors
__device__ int   g_bsum[1024];
__device__ int   g_bscan[1024];
__device__ unsigned g_entries[RE];             // src node per CSR entry
__device__ __nv_bfloat16 g_xb[Nn*Ff];          // bf16 copy of x (25.6 MB, L2-resident)
__device__ __nv_bfloat16 g_Whi[Rr*Ff*Ff];      // bf16 W1, high part  (192KB, L2-resident)
__device__ __nv_bfloat16 g_Wlo[Rr*Ff*Ff];      // bf16 W1, residual
__device__ float g_b1sum[Ff];                  // sum_r b1[r]
__device__ float g_csum[NR];                   // per (r,src): sum over out-edges of norm_dst[dst]
__device__ float g_M[Rr*Ff];                   // M[r] = sum_n w_r[n] * relu(h1[n])

// ---------------- setup kernels ----------------------------------------------
__global__ void k_zero() {
    int i = blockIdx.x * blockDim.x + threadIdx.x;
    if (i < NR) { g_cntout[i] = 0; g_counts[i] = 0; g_csum[i] = 0.f; }
    if (i < Rr*Ff) g_M[i] = 0.f;
}

__global__ void k_xconv(const float* __restrict__ x) {
    int i = blockIdx.x * blockDim.x + threadIdx.x;
    if (i < Nn*Ff) g_xb[i] = __float2bfloat16(x[i]);
}

__global__ void k_wconv(const float* __restrict__ W1, const float* __restrict__ b1) {
    int i = blockIdx.x * blockDim.x + threadIdx.x;
    if (i < Rr*Ff*Ff) {
        float w = W1[i];
        __nv_bfloat16 hi = __float2bfloat16(w);
        g_Whi[i] = hi;
        g_Wlo[i] = __float2bfloat16(w - __bfloat162float(hi));
    }
    if (i < Ff) {
        float s = 0.f;
        for (int r = 0; r < Rr; r++) s += b1[r*Ff + i];
        g_b1sum[i] = s;
    }
}

// out-degree + CSR row histogram (in-degree) — 2 atomics per edge
__global__ void k_deg(const int* __restrict__ src, const int* __restrict__ dst) {
    int i = blockIdx.x * blockDim.x + threadIdx.x;
    if (i >= RE) return;
    int r = i / Ee;
    atomicAdd(&g_cntout[r*Nn + src[i]], 1);
    atomicAdd(&g_counts[dst[i]*Rr + r], 1);
}

__global__ void k_norm() {
    int i = blockIdx.x * blockDim.x + threadIdx.x;
    if (i >= NR) return;
    int r = i / Nn, n = i - r*Nn;
    int a = g_cntout[i];
    int b = g_counts[n*Rr + r];
    g_ns[i] = (a > 0) ? rsqrtf((float)a) : 0.f;
    g_nd[i] = (b > 0) ? rsqrtf((float)b) : 0.f;
}

__global__ void k_scan1() {
    __shared__ int s[1024];
    int b = blockIdx.x, t = threadIdx.x, i = b*1024 + t;
    int v = (i < NR) ? g_counts[i] : 0;
    s[t] = v; __syncthreads();
    for (int off = 1; off < 1024; off <<= 1) {
        int tv = (t >= off) ? s[t-off] : 0;
        __syncthreads(); s[t] += tv; __syncthreads();
    }
    if (i < NR) g_off[i] = s[t] - v;
    if (t == 1023) g_bsum[b] = s[1023];
}

__global__ void k_scan2() {
    __shared__ int s[1024];
    int t = threadIdx.x;
    int v = (t < SCAN_BLKS) ? g_bsum[t] : 0;
    s[t] = v; __syncthreads();
    for (int off = 1; off < 1024; off <<= 1) {
        int tv = (t >= off) ? s[t-off] : 0;
        __syncthreads(); s[t] += tv; __syncthreads();
    }
    g_bscan[t] = s[t] - v;
}

__global__ void k_scan3() {
    int i = blockIdx.x * blockDim.x + threadIdx.x;
    if (i >= NR) return;
    int o = g_off[i] + g_bscan[i >> 10];
    g_off[i] = o;
    g_cursor[i] = o;
}

// scatter CSR entries + layer-2 coefficient sums in one edge pass
__global__ void k_scatter(const int* __restrict__ src, const int* __restrict__ dst) {
    int i = blockIdx.x * blockDim.x + threadIdx.x;
    if (i >= RE) return;
    int r = i / Ee;
    int s = src[i], d = dst[i];
    int pos = atomicAdd(&g_cursor[d*Rr + r], 1);
    g_entries[pos] = (unsigned)s;
    atomicAdd(&g_csum[r*Nn + s], g_nd[r*Nn + d]);
}

// ---------------- fused aggregate + GEMM + M-reduction ------------------------
// Per 128-dst block: for each relation r, aggregate the [128,128] tile into
// smem (bf16), then MMA against Whi_r/Wlo_r (staged per 32-K chunk), summing
// all relations into fp32 accumulators. Epilogue: relu + bias, then weighted
// reduction into g_M. h1 and agg never touch global memory.
__global__ void k_fused() {
    __shared__ __align__(16) char sm[49152];
    __nv_bfloat16* Ag = reinterpret_cast<__nv_bfloat16*>(sm);          // 128x128 (32KB)
    __nv_bfloat16* Bh = reinterpret_cast<__nv_bfloat16*>(sm + 32768);  // 32x128  (8KB)
    __nv_bfloat16* Bl = reinterpret_cast<__nv_bfloat16*>(sm + 40960);  // 32x128  (8KB)
    int t = threadIdx.x, warp = t >> 5, lane = t & 31;
    int wm = warp >> 2, wn = warp & 3;          // 2 x 4 warp grid, each 64x32 of C
    int rowbase = blockIdx.x * MBLK;

    wmma::fragment<wmma::accumulator, 16, 16, 16, float> acc[4][2];
    #pragma unroll
    for (int i = 0; i < 4; i++)
        #pragma unroll
        for (int j = 0; j < 2; j++) wmma::fill_fragment(acc[i][j], 0.f);

    for (int r = 0; r < Rr; r++) {
        // ---- aggregate relation r tile into Ag ----
        for (int rowi = warp; rowi < MBLK; rowi += 8) {
            int dst = rowbase + rowi;
            float4 a = make_float4(0.f, 0.f, 0.f, 0.f);
            if (dst < Nn) {
                int rid = dst*Rr + r;
                int start = g_off[rid], cnt = g_counts[rid];
                for (int base = 0; base < cnt; base += 32) {
                    int j = base + lane;
                    int e = 0; float w = 0.f;
                    if (j < cnt) { e = (int)g_entries[start + j]; w = g_ns[r*Nn + e]; }
                    int m = min(32, cnt - base);
                    int k = 0;
                    for (; k + 1 < m; k += 2) {         // 2 gathers in flight
                        int   s0 = __shfl_sync(0xffffffffu, e, k);
                        float w0 = __shfl_sync(0xffffffffu, w, k);
                        int   s1 = __shfl_sync(0xffffffffu, e, k+1);
                        float w1 = __shfl_sync(0xffffffffu, w, k+1);
                        uint2 u0 = reinterpret_cast<const uint2*>(g_xb + s0*Ff)[lane];
                        uint2 u1 = reinterpret_cast<const uint2*>(g_xb + s1*Ff)[lane];
                        float2 a0 = __bfloat1622float2(*reinterpret_cast<__nv_bfloat162*>(&u0.x));
                        float2 b0 = __bfloat1622float2(*reinterpret_cast<__nv_bfloat162*>(&u0.y));
                        float2 a1 = __bfloat1622float2(*reinterpret_cast<__nv_bfloat162*>(&u1.x));
                        float2 b1 = __bfloat1622float2(*reinterpret_cast<__nv_bfloat162*>(&u1.y));
                        a.x += w0*a0.x + w1*a1.x;  a.y += w0*a0.y + w1*a1.y;
                        a.z += w0*b0.x + w1*b1.x;  a.w += w0*b0.y + w1*b1.y;
                    }
                    if (k < m) {
                        int   s0 = __shfl_sync(0xffffffffu, e, k);
                        float w0 = __shfl_sync(0xffffffffu, w, k);
                        uint2 u0 = reinterpret_cast<const uint2*>(g_xb + s0*Ff)[lane];
                        float2 a0 = __bfloat1622float2(*reinterpret_cast<__nv_bfloat162*>(&u0.x));
                        float2 b0 = __bfloat1622float2(*reinterpret_cast<__nv_bfloat162*>(&u0.y));
                        a.x += w0*a0.x;  a.y += w0*a0.y;
                        a.z += w0*b0.x;  a.w += w0*b0.y;
                    }
                }
                float nd = g_nd[r*Nn + dst];
                a.x *= nd; a.y *= nd; a.z *= nd; a.w *= nd;
            }
            __nv_bfloat162 o0 = __floats2bfloat162_rn(a.x, a.y);
            __nv_bfloat162 o1 = __floats2bfloat162_rn(a.z, a.w);
            uint2 ou;
            ou.x = *reinterpret_cast<unsigned*>(&o0);
            ou.y = *reinterpret_cast<unsigned*>(&o1);
            reinterpret_cast<uint2*>(Ag + rowi*Ff)[lane] = ou;
        }

        // ---- MMA: C += Ag @ (Whi_r + Wlo_r), K=128 in 32-chunks ----
        const __nv_bfloat16* Wh = g_Whi + r*Ff*Ff;
        const __nv_bfloat16* Wl = g_Wlo + r*Ff*Ff;
        for (int kk = 0; kk < Ff; kk += 32) {
            __syncthreads();    // Ag ready (first chunk) / B chunk consumed (later)
            #pragma unroll
            for (int u = t; u < 512; u += 256) {
                int row = u >> 4, c = (u & 15) * 8;
                *reinterpret_cast<uint4*>(Bh + row*128 + c) =
                    *reinterpret_cast<const uint4*>(Wh + (kk + row)*128 + c);
                *reinterpret_cast<uint4*>(Bl + row*128 + c) =
                    *reinterpret_cast<const uint4*>(Wl + (kk + row)*128 + c);
            }
            __syncthreads();
            #pragma unroll
            for (int kf = 0; kf < 32; kf += 16) {
                wmma::fragment<wmma::matrix_a, 16, 16, 16, __nv_bfloat16, wmma::row_major> af[4];
                wmma::fragment<wmma::matrix_b, 16, 16, 16, __nv_bfloat16, wmma::row_major> bh[2], bl[2];
                #pragma unroll
                for (int i = 0; i < 4; i++)
                    wmma::load_matrix_sync(af[i], Ag + (wm*64 + i*16)*Ff + kk + kf, Ff);
                #pragma unroll
                for (int j = 0; j < 2; j++) {
                    wmma::load_matrix_sync(bh[j], Bh + kf*128 + wn*32 + j*16, 128);
                    wmma::load_matrix_sync(bl[j], Bl + kf*128 + wn*32 + j*16, 128);
                }
                #pragma unroll
                for (int i = 0; i < 4; i++)
                    #pragma unroll
                    for (int j = 0; j < 2; j++) {
                        wmma::mma_sync(acc[i][j], af[i], bh[j], acc[i][j]);
                        wmma::mma_sync(acc[i][j], af[i], bl[j], acc[i][j]);
                    }
            }
        }
        __syncthreads();        // before next relation overwrites Ag
    }

    // ---- fused epilogue: relu + bias, weighted reduction into g_M ----
    float* Cs = reinterpret_cast<float*>(sm);                // 64x128 f32 (32KB)
    float* wc = reinterpret_cast<float*>(sm + 32768);        // [6][64]   (1.5KB)
    float* Mp = reinterpret_cast<float*>(sm + 32768 + 1536); // [2][6][128] (6KB)

    int col  = t & 127;
    int half = t >> 7;
    float b1s = g_b1sum[col];
    float ma[Rr];
    #pragma unroll
    for (int r = 0; r < Rr; r++) ma[r] = 0.f;

    #pragma unroll
    for (int p = 0; p < 2; p++) {
        if (wm == p) {
            #pragma unroll
            for (int i = 0; i < 4; i++)
                #pragma unroll
                for (int j = 0; j < 2; j++)
                    wmma::store_matrix_sync(Cs + (i*16)*128 + wn*32 + j*16,
                                            acc[i][j], 128, wmma::mem_row_major);
        }
        for (int u = t; u < Rr*64; u += 256) {
            int r = u >> 6, row = u & 63;
            int gr = rowbase + p*64 + row;
            wc[r*64 + row] = (gr < Nn) ? g_ns[r*Nn + gr] * g_csum[r*Nn + gr] : 0.f;
        }
        __syncthreads();
        #pragma unroll 4
        for (int rw = 0; rw < 32; rw++) {
            int row = half*32 + rw;
            float v = fmaxf(Cs[row*128 + col] + b1s, 0.f);   // h1 element (fp32)
            #pragma unroll
            for (int r = 0; r < Rr; r++)
                ma[r] += wc[r*64 + row] * v;
        }
        __syncthreads();
    }
    #pragma unroll
    for (int r = 0; r < Rr; r++) Mp[(half*Rr + r)*128 + col] = ma[r];
    __syncthreads();
    for (int u = t; u < Rr*Ff; u += 256)
        atomicAdd(&g_M[u], Mp[u] + Mp[Rr*Ff + u]);
}

// g = (1/N) sum_r M[r] @ W2_r + sum_r b2_r ; out = g @ Wc + bc
__global__ void k_out(const float* __restrict__ W2, const float* __restrict__ b2,
                      const float* __restrict__ Wc, const float* __restrict__ bc,
                      float* __restrict__ out) {
    __shared__ float g[Ff];
    int t = threadIdx.x;
    float acc = 0.f, bb = 0.f;
    for (int r = 0; r < Rr; r++) {
        const float* W2r = W2 + r*Ff*Ff;
        for (int h = 0; h < Ff; h++)
            acc += g_M[r*Ff + h] * W2r[h*Ff + t];
        bb += b2[r*Ff + t];
    }
    g[t] = acc * (1.f / (float)Nn) + bb;
    __syncthreads();
    if (t < 2) {
        float o = bc[t];
        for (int h = 0; h < Ff; h++) o += g[h] * Wc[h*2 + t];
        out[t] = o;
    }
}

// ---------------- launch ------------------------------------------------------
extern "C" void kernel_launch(void* const* d_in, const int* in_sizes, int n_in,
                              void* d_out, int out_size) {
    const float* x    = (const float*)d_in[0];
    const int*   esrc = (const int*)  d_in[1];
    const int*   edst = (const int*)  d_in[2];
    const float* W1   = (const float*)d_in[3];
    const float* b1   = (const float*)d_in[4];
    const float* W2   = (const float*)d_in[5];
    const float* b2   = (const float*)d_in[6];
    const float* Wc   = (const float*)d_in[7];
    const float* bc   = (const float*)d_in[8];
    float* out = (float*)d_out;

    k_zero   <<<(NR + 255)/256, 256>>>();
    k_xconv  <<<(Nn*Ff + 255)/256, 256>>>(x);
    k_wconv  <<<(Rr*Ff*Ff + 255)/256, 256>>>(W1, b1);
    k_deg    <<<(RE + 255)/256, 256>>>(esrc, edst);
    k_norm   <<<(NR + 255)/256, 256>>>();
    k_scan1  <<<SCAN_BLKS, 1024>>>();
    k_scan2  <<<1, 1024>>>();
    k_scan3  <<<SCAN_BLKS, 1024>>>();
    k_scatter<<<(RE + 255)/256, 256>>>(esrc, edst);
    k_fused  <<<NBLKS, 256>>>();
    k_out    <<<1, 128>>>(W2, b2, Wc, bc, out);
}

// round 8
// speedup vs baseline: 1.0216x; 1.0216x over previous
#include <cuda_runtime.h>
#include <cuda_bf16.h>
#include <mma.h>

using namespace nvcuda;

#define Nn 100000
#define Rr 6
#define Ee 400000
#define Ff 128
#define RE (Rr*Ee)        // 2,400,000 edges total
#define NR (Nn*Rr)        // 600,000 (dst,rel) rows
#define SCAN_BLKS 586     // ceil(NR/1024)
#define MBLK 128
#define NBLKS ((Nn + MBLK - 1) / MBLK)   // 782
#define NTHR 512

// ---------------- scratch (__device__ globals; no runtime alloc) -------------
__device__ int   g_cntout[NR];                 // out-degree per (r,src)
__device__ int   g_counts[NR];                 // CSR row counts, row = dst*Rr+r (== in-degree)
__device__ float g_ns[NR];                     // norm_src per (r,n)
__device__ float g_nd[NR];                     // norm_dst per (r,n)
__device__ int   g_off[NR];                    // CSR row offsets (exclusive)
__device__ int   g_cursor[NR];                 // scatter cursors
__device__ int   g_bsum[1024];
__device__ int   g_bscan[1024];
__device__ unsigned g_entries[RE];             // src node per CSR entry
__device__ __nv_bfloat16 g_xb[Nn*Ff];          // bf16 copy of x (25.6 MB, L2-resident)
__device__ __nv_bfloat16 g_Whi[Rr*Ff*Ff];      // bf16 W1, high part
__device__ __nv_bfloat16 g_Wlo[Rr*Ff*Ff];      // bf16 W1, residual
__device__ float g_b1sum[Ff];                  // sum_r b1[r]
__device__ float g_csum[NR];                   // per (r,src): sum over out-edges of norm_dst[dst]
__device__ float g_M[Rr*Ff];                   // M[r] = sum_n w_r[n] * relu(h1[n])

// ---------------- setup kernels ----------------------------------------------
__global__ void k_zero() {
    int i = blockIdx.x * blockDim.x + threadIdx.x;
    if (i < NR) { g_cntout[i] = 0; g_counts[i] = 0; g_csum[i] = 0.f; }
    if (i < Rr*Ff) g_M[i] = 0.f;
}

__global__ void k_xconv(const float* __restrict__ x) {
    int i = blockIdx.x * blockDim.x + threadIdx.x;
    if (i < Nn*Ff) g_xb[i] = __float2bfloat16(x[i]);
}

__global__ void k_wconv(const float* __restrict__ W1, const float* __restrict__ b1) {
    int i = blockIdx.x * blockDim.x + threadIdx.x;
    if (i < Rr*Ff*Ff) {
        float w = W1[i];
        __nv_bfloat16 hi = __float2bfloat16(w);
        g_Whi[i] = hi;
        g_Wlo[i] = __float2bfloat16(w - __bfloat162float(hi));
    }
    if (i < Ff) {
        float s = 0.f;
        for (int r = 0; r < Rr; r++) s += b1[r*Ff + i];
        g_b1sum[i] = s;
    }
}

__global__ void k_deg(const int* __restrict__ src, const int* __restrict__ dst) {
    int i = blockIdx.x * blockDim.x + threadIdx.x;
    if (i >= RE) return;
    int r = i / Ee;
    atomicAdd(&g_cntout[r*Nn + src[i]], 1);
    atomicAdd(&g_counts[dst[i]*Rr + r], 1);
}

__global__ void k_norm() {
    int i = blockIdx.x * blockDim.x + threadIdx.x;
    if (i >= NR) return;
    int r = i / Nn, n = i - r*Nn;
    int a = g_cntout[i];
    int b = g_counts[n*Rr + r];
    g_ns[i] = (a > 0) ? rsqrtf((float)a) : 0.f;
    g_nd[i] = (b > 0) ? rsqrtf((float)b) : 0.f;
}

__global__ void k_scan1() {
    __shared__ int s[1024];
    int b = blockIdx.x, t = threadIdx.x, i = b*1024 + t;
    int v = (i < NR) ? g_counts[i] : 0;
    s[t] = v; __syncthreads();
    for (int off = 1; off < 1024; off <<= 1) {
        int tv = (t >= off) ? s[t-off] : 0;
        __syncthreads(); s[t] += tv; __syncthreads();
    }
    if (i < NR) g_off[i] = s[t] - v;
    if (t == 1023) g_bsum[b] = s[1023];
}

__global__ void k_scan2() {
    __shared__ int s[1024];
    int t = threadIdx.x;
    int v = (t < SCAN_BLKS) ? g_bsum[t] : 0;
    s[t] = v; __syncthreads();
    for (int off = 1; off < 1024; off <<= 1) {
        int tv = (t >= off) ? s[t-off] : 0;
        __syncthreads(); s[t] += tv; __syncthreads();
    }
    g_bscan[t] = s[t] - v;
}

__global__ void k_scan3() {
    int i = blockIdx.x * blockDim.x + threadIdx.x;
    if (i >= NR) return;
    int o = g_off[i] + g_bscan[i >> 10];
    g_off[i] = o;
    g_cursor[i] = o;
}

// scatter CSR entries + layer-2 coefficient sums in one edge pass
__global__ void k_scatter(const int* __restrict__ src, const int* __restrict__ dst) {
    int i = blockIdx.x * blockDim.x + threadIdx.x;
    if (i >= RE) return;
    int r = i / Ee;
    int s = src[i], d = dst[i];
    int pos = atomicAdd(&g_cursor[d*Rr + r], 1);
    g_entries[pos] = (unsigned)s;
    atomicAdd(&g_csum[r*Nn + s], g_nd[r*Nn + d]);
}

// ---------------- fused aggregate + GEMM + M-reduction ------------------------
// 512 threads / 16 warps, 2 blocks/SM. Per 128-dst block: per relation,
// 16 warps aggregate 8 rows each into smem (bf16), then 16 warps MMA the
// tile against Whi_r/Wlo_r (32x32 C per warp). Epilogue: relu+bias and
// weighted reduction into g_M over two 64-row passes.
__global__ void __launch_bounds__(NTHR, 2) k_fused() {
    __shared__ __align__(16) char sm[49152];
    __nv_bfloat16* Ag = reinterpret_cast<__nv_bfloat16*>(sm);          // 128x128 (32KB)
    __nv_bfloat16* Bh = reinterpret_cast<__nv_bfloat16*>(sm + 32768);  // 32x128  (8KB)
    __nv_bfloat16* Bl = reinterpret_cast<__nv_bfloat16*>(sm + 40960);  // 32x128  (8KB)
    int t = threadIdx.x, warp = t >> 5, lane = t & 31;
    int wm = warp >> 2, wn = warp & 3;          // 4 x 4 warp grid, each 32x32 of C
    int rowbase = blockIdx.x * MBLK;

    wmma::fragment<wmma::accumulator, 16, 16, 16, float> acc[2][2];
    #pragma unroll
    for (int i = 0; i < 2; i++)
        #pragma unroll
        for (int j = 0; j < 2; j++) wmma::fill_fragment(acc[i][j], 0.f);

    for (int r = 0; r < Rr; r++) {
        // ---- aggregate relation r tile into Ag (16 warps x 8 rows) ----
        for (int rowi = warp; rowi < MBLK; rowi += 16) {
            int dst = rowbase + rowi;
            float4 a = make_float4(0.f, 0.f, 0.f, 0.f);
            if (dst < Nn) {
                int rid = dst*Rr + r;
                int start = g_off[rid], cnt = g_counts[rid];
                for (int base = 0; base < cnt; base += 32) {
                    int j = base + lane;
                    int e = 0; float w = 0.f;
                    if (j < cnt) { e = (int)g_entries[start + j]; w = g_ns[r*Nn + e]; }
                    int m = min(32, cnt - base);
                    int k = 0;
                    for (; k + 1 < m; k += 2) {         // 2 gathers in flight
                        int   s0 = __shfl_sync(0xffffffffu, e, k);
                        float w0 = __shfl_sync(0xffffffffu, w, k);
                        int   s1 = __shfl_sync(0xffffffffu, e, k+1);
                        float w1 = __shfl_sync(0xffffffffu, w, k+1);
                        uint2 u0 = reinterpret_cast<const uint2*>(g_xb + s0*Ff)[lane];
                        uint2 u1 = reinterpret_cast<const uint2*>(g_xb + s1*Ff)[lane];
                        float2 a0 = __bfloat1622float2(*reinterpret_cast<__nv_bfloat162*>(&u0.x));
                        float2 b0 = __bfloat1622float2(*reinterpret_cast<__nv_bfloat162*>(&u0.y));
                        float2 a1 = __bfloat1622float2(*reinterpret_cast<__nv_bfloat162*>(&u1.x));
                        float2 b1 = __bfloat1622float2(*reinterpret_cast<__nv_bfloat162*>(&u1.y));
                        a.x += w0*a0.x + w1*a1.x;  a.y += w0*a0.y + w1*a1.y;
                        a.z += w0*b0.x + w1*b1.x;  a.w += w0*b0.y + w1*b1.y;
                    }
                    if (k < m) {
                        int   s0 = __shfl_sync(0xffffffffu, e, k);
                        float w0 = __shfl_sync(0xffffffffu, w, k);
                        uint2 u0 = reinterpret_cast<const uint2*>(g_xb + s0*Ff)[lane];
                        float2 a0 = __bfloat1622float2(*reinterpret_cast<__nv_bfloat162*>(&u0.x));
                        float2 b0 = __bfloat1622float2(*reinterpret_cast<__nv_bfloat162*>(&u0.y));
                        a.x += w0*a0.x;  a.y += w0*a0.y;
                        a.z += w0*b0.x;  a.w += w0*b0.y;
                    }
                }
                float nd = g_nd[r*Nn + dst];
                a.x *= nd; a.y *= nd; a.z *= nd; a.w *= nd;
            }
            __nv_bfloat162 o0 = __floats2bfloat162_rn(a.x, a.y);
            __nv_bfloat162 o1 = __floats2bfloat162_rn(a.z, a.w);
            uint2 ou;
            ou.x = *reinterpret_cast<unsigned*>(&o0);
            ou.y = *reinterpret_cast<unsigned*>(&o1);
            reinterpret_cast<uint2*>(Ag + rowi*Ff)[lane] = ou;
        }

        // ---- MMA: C += Ag @ (Whi_r + Wlo_r), K=128 in 32-chunks ----
        const __nv_bfloat16* Wh = g_Whi + r*Ff*Ff;
        const __nv_bfloat16* Wl = g_Wlo + r*Ff*Ff;
        for (int kk = 0; kk < Ff; kk += 32) {
            __syncthreads();    // Ag ready (first chunk) / prev B chunk consumed
            {                   // stage B chunk: 512 threads x 1 uint4 per buffer
                int row = t >> 4, c = (t & 15) * 8;
                *reinterpret_cast<uint4*>(Bh + row*128 + c) =
                    *reinterpret_cast<const uint4*>(Wh + (kk + row)*128 + c);
                *reinterpret_cast<uint4*>(Bl + row*128 + c) =
                    *reinterpret_cast<const uint4*>(Wl + (kk + row)*128 + c);
            }
            __syncthreads();
            #pragma unroll
            for (int kf = 0; kf < 32; kf += 16) {
                #pragma unroll
                for (int i = 0; i < 2; i++) {
                    wmma::fragment<wmma::matrix_a, 16, 16, 16, __nv_bfloat16, wmma::row_major> af;
                    wmma::load_matrix_sync(af, Ag + (wm*32 + i*16)*Ff + kk + kf, Ff);
                    #pragma unroll
                    for (int j = 0; j < 2; j++) {
                        wmma::fragment<wmma::matrix_b, 16, 16, 16, __nv_bfloat16, wmma::row_major> bf;
                        wmma::load_matrix_sync(bf, Bh + kf*128 + wn*32 + j*16, 128);
                        wmma::mma_sync(acc[i][j], af, bf, acc[i][j]);
                        wmma::load_matrix_sync(bf, Bl + kf*128 + wn*32 + j*16, 128);
                        wmma::mma_sync(acc[i][j], af, bf, acc[i][j]);
                    }
                }
            }
        }
        __syncthreads();        // last MMA done before next relation overwrites Ag
    }

    // ---- fused epilogue: relu + bias, weighted reduction into g_M ----
    float* Cs = reinterpret_cast<float*>(sm);                // 64x128 f32 (32KB)
    float* wc = reinterpret_cast<float*>(sm + 32768);        // [6][128]  (3KB)
    float* Mp = reinterpret_cast<float*>(sm + 35840);        // [4][6][128] (12KB)

    int col = t & 127;
    int q   = t >> 7;                    // thread quarter 0..3
    float b1s = g_b1sum[col];
    float ma[Rr];
    #pragma unroll
    for (int r = 0; r < Rr; r++) ma[r] = 0.f;

    // per-row weights for the whole 128-row tile
    for (int u = t; u < Rr*MBLK; u += NTHR) {
        int r = u >> 7, row = u & 127;
        int gr = rowbase + row;
        wc[u] = (gr < Nn) ? g_ns[r*Nn + gr] * g_csum[r*Nn + gr] : 0.f;
    }

    #pragma unroll
    for (int p = 0; p < 2; p++) {
        __syncthreads();                  // smem free / prev pass consumed; wc visible
        if ((wm >> 1) == p) {             // warps owning rows [p*64, p*64+64)
            #pragma unroll
            for (int i = 0; i < 2; i++)
                #pragma unroll
                for (int j = 0; j < 2; j++)
                    wmma::store_matrix_sync(Cs + ((wm & 1)*32 + i*16)*128 + wn*32 + j*16,
                                            acc[i][j], 128, wmma::mem_row_major);
        }
        __syncthreads();
        #pragma unroll 4
        for (int rw = 0; rw < 16; rw++) {
            int row64 = q*16 + rw;                     // 0..63 within pass
            int grow  = p*64 + row64;                  // 0..127 within tile
            float v = fmaxf(Cs[row64*128 + col] + b1s, 0.f);   // h1 (fp32)
            #pragma unroll
            for (int r = 0; r < Rr; r++)
                ma[r] += wc[r*MBLK + grow] * v;
        }
    }
    __syncthreads();
    #pragma unroll
    for (int r = 0; r < Rr; r++) Mp[(q*Rr + r)*128 + col] = ma[r];
    __syncthreads();
    for (int u = t; u < Rr*Ff; u += NTHR)
        atomicAdd(&g_M[u], Mp[u] + Mp[768 + u] + Mp[1536 + u] + Mp[2304 + u]);
}

// g = (1/N) sum_r M[r] @ W2_r + sum_r b2_r ; out = g @ Wc + bc
__global__ void k_out(const float* __restrict__ W2, const float* __restrict__ b2,
                      const float* __restrict__ Wc, const float* __restrict__ bc,
                      float* __restrict__ out) {
    __shared__ float g[Ff];
    int t = threadIdx.x;
    float acc = 0.f, bb = 0.f;
    for (int r = 0; r < Rr; r++) {
        const float* W2r = W2 + r*Ff*Ff;
        for (int h = 0; h < Ff; h++)
            acc += g_M[r*Ff + h] * W2r[h*Ff + t];
        bb += b2[r*Ff + t];
    }
    g[t] = acc * (1.f / (float)Nn) + bb;
    __syncthreads();
    if (t < 2) {
        float o = bc[t];
        for (int h = 0; h < Ff; h++) o += g[h] * Wc[h*2 + t];
        out[t] = o;
    }
}

// ---------------- launch ------------------------------------------------------
extern "C" void kernel_launch(void* const* d_in, const int* in_sizes, int n_in,
                              void* d_out, int out_size) {
    const float* x    = (const float*)d_in[0];
    const int*   esrc = (const int*)  d_in[1];
    const int*   edst = (const int*)  d_in[2];
    const float* W1   = (const float*)d_in[3];
    const float* b1   = (const float*)d_in[4];
    const float* W2   = (const float*)d_in[5];
    const float* b2   = (const float*)d_in[6];
    const float* Wc   = (const float*)d_in[7];
    const float* bc   = (const float*)d_in[8];
    float* out = (float*)d_out;

    k_zero   <<<(NR + 255)/256, 256>>>();
    k_xconv  <<<(Nn*Ff + 255)/256, 256>>>(x);
    k_wconv  <<<(Rr*Ff*Ff + 255)/256, 256>>>(W1, b1);
    k_deg    <<<(RE + 255)/256, 256>>>(esrc, edst);
    k_norm   <<<(NR + 255)/256, 256>>>();
    k_scan1  <<<SCAN_BLKS, 1024>>>();
    k_scan2  <<<1, 1024>>>();
    k_scan3  <<<SCAN_BLKS, 1024>>>();
    k_scatter<<<(RE + 255)/256, 256>>>(esrc, edst);
    k_fused  <<<NBLKS, NTHR>>>();
    k_out    <<<1, 128>>>(W2, b2, Wc, bc, out);
}

// round 11
// speedup vs baseline: 1.0753x; 1.0526x over previous
#include <cuda_runtime.h>
#include <cuda_bf16.h>
#include <mma.h>

using namespace nvcuda;

#define Nn 100000
#define Rr 6
#define Ee 400000
#define Ff 128
#define RE (Rr*Ee)        // 2,400,000 edges total
#define NR (Nn*Rr)        // 600,000 (dst,rel) CSR rows
#define MBLK 128
#define NBLKS ((Nn + MBLK - 1) / MBLK)   // 782
#define NTHR 512

// ---------------- scratch (__device__ globals; no runtime alloc) -------------
__device__ int   g_cntout[NR];                 // out-degree per (r,src)
__device__ int   g_counts[NR];                 // in-degree per CSR row (dst*Rr+r)
__device__ float g_ns[NR];                     // norm_src per (r,n)
__device__ float g_nd[NR];                     // norm_dst per (r,n)
__device__ int   g_off[NR];                    // CSR segment starts (atomic-reserved)
__device__ int   g_cursor[NR];                 // scatter cursors
__device__ int   g_total;                      // global segment allocator
__device__ uint2 g_ent[RE];                    // (src, ns[src] bits) per CSR entry
__device__ __nv_bfloat16 g_xb[Nn*Ff];          // bf16 x (25.6 MB, L2-resident)
__device__ __nv_bfloat16 g_Whi[Rr*Ff*Ff];      // bf16 W1 high part
__device__ __nv_bfloat16 g_Wlo[Rr*Ff*Ff];      // bf16 W1 residual
__device__ float g_b1sum[Ff];                  // sum_r b1[r]
__device__ float g_csum[NR];                   // per (r,src): sum of nd[dst] over out-edges
__device__ float g_wc[NR];                     // ns * csum  (layer-2 row weights)
__device__ float g_M[Rr*Ff];                   // M[r] = sum_n wc_r[n] * relu(h1[n])

// ---------------- setup -------------------------------------------------------
// zero + x->bf16 + W1 hi/lo split + b1 sum, one kernel
__global__ void k_init(const float* __restrict__ x,
                       const float* __restrict__ W1, const float* __restrict__ b1) {
    int i = blockIdx.x * blockDim.x + threadIdx.x;
    if (i < NR) { g_cntout[i] = 0; g_counts[i] = 0; g_csum[i] = 0.f; }
    if (i == 0) g_total = 0;
    if (i < Nn*Ff) g_xb[i] = __float2bfloat16(x[i]);
    if (i < Rr*Ff*Ff) {
        float w = W1[i];
        __nv_bfloat16 hi = __float2bfloat16(w);
        g_Whi[i] = hi;
        g_Wlo[i] = __float2bfloat16(w - __bfloat162float(hi));
    }
    if (i < Ff) {
        float s = 0.f;
        for (int r = 0; r < Rr; r++) s += b1[r*Ff + i];
        g_b1sum[i] = s;
    }
}

__global__ void k_deg(const int* __restrict__ src, const int* __restrict__ dst) {
    int i = blockIdx.x * blockDim.x + threadIdx.x;
    if (i >= RE) return;
    int r = i / Ee;
    atomicAdd(&g_cntout[r*Nn + src[i]], 1);
    atomicAdd(&g_counts[dst[i]*Rr + r], 1);
}

// norms + CSR segment reservation (order-free: only disjointness matters)
__global__ void k_norm() {
    int i = blockIdx.x * blockDim.x + threadIdx.x;
    if (i >= NR) return;
    int r = i / Nn, n = i - r*Nn;
    int a = g_cntout[i];
    int b = g_counts[n*Rr + r];
    g_ns[i] = (a > 0) ? rsqrtf((float)a) : 0.f;
    g_nd[i] = (b > 0) ? rsqrtf((float)b) : 0.f;
    int cnt = g_counts[i];                 // i as CSR row (dst*Rr+r)
    int off = atomicAdd(&g_total, cnt);
    g_off[i] = off;
    g_cursor[i] = off;
}

// scatter (src, ns[src]) entries + layer-2 coefficient sums in one edge pass
__global__ void k_scatter(const int* __restrict__ src, const int* __restrict__ dst) {
    int i = blockIdx.x * blockDim.x + threadIdx.x;
    if (i >= RE) return;
    int r = i / Ee;
    int s = src[i], d = dst[i];
    int pos = atomicAdd(&g_cursor[d*Rr + r], 1);
    float w = g_ns[r*Nn + s];
    g_ent[pos] = make_uint2((unsigned)s, __float_as_uint(w));
    atomicAdd(&g_csum[r*Nn + s], g_nd[r*Nn + d]);
}

// epilogue row weights + M zeroing
__global__ void k_pre() {
    int i = blockIdx.x * blockDim.x + threadIdx.x;
    if (i < NR) g_wc[i] = g_ns[i] * g_csum[i];
    if (i < Rr*Ff) g_M[i] = 0.f;
}

// ---------------- fused aggregate + GEMM + M-reduction ------------------------
// 512 threads / 16 warps, 2 blocks/SM. Per 128-dst tile: per relation,
// 16 warps aggregate 8 rows each into smem bf16 (meta software-pipelined,
// edge gather unrolled x4), then MMA vs Whi/Wlo loaded DIRECT from global
// (L1/L2-resident) -- only 2 barriers per relation. Epilogue: relu+bias,
// weighted reduction into g_M.
__global__ void __launch_bounds__(NTHR, 2) k_fused() {
    __shared__ __align__(16) char sm[48128];
    __nv_bfloat16* Ag = reinterpret_cast<__nv_bfloat16*>(sm);          // 128x128 (32KB)
    int t = threadIdx.x, warp = t >> 5, lane = t & 31;
    int wm = warp >> 2, wn = warp & 3;          // 4 x 4 warp grid, each 32x32 of C
    int rowbase = blockIdx.x * MBLK;

    wmma::fragment<wmma::accumulator, 16, 16, 16, float> acc[2][2];
    #pragma unroll
    for (int i = 0; i < 2; i++)
        #pragma unroll
        for (int j = 0; j < 2; j++) wmma::fill_fragment(acc[i][j], 0.f);

    for (int r = 0; r < Rr; r++) {
        // ---- aggregate: 8 rows per warp, meta pipelined one row ahead ----
        int rowi = warp;
        int off_c = 0, cnt_c = 0; float nd_c = 0.f;
        {
            int dst = rowbase + rowi;
            if (dst < Nn) {
                int rid = dst*Rr + r;
                off_c = g_off[rid]; cnt_c = g_counts[rid]; nd_c = g_nd[r*Nn + dst];
            }
        }
        #pragma unroll
        for (int it = 0; it < 8; it++) {
            int rowi_n = rowi + 16;
            int off_n = 0, cnt_n = 0; float nd_n = 0.f;
            if (it < 7) {
                int dstn = rowbase + rowi_n;
                if (dstn < Nn) {
                    int ridn = dstn*Rr + r;
                    off_n = g_off[ridn]; cnt_n = g_counts[ridn]; nd_n = g_nd[r*Nn + dstn];
                }
            }
            // process current row
            float4 a = make_float4(0.f, 0.f, 0.f, 0.f);
            {
                const uint2* ep = g_ent + off_c;
                int k = 0;
                for (; k + 4 <= cnt_c; k += 4) {          // 4 gathers in flight
                    uint2 e0 = ep[k+0], e1 = ep[k+1], e2 = ep[k+2], e3 = ep[k+3];
                    uint2 u0 = reinterpret_cast<const uint2*>(g_xb + e0.x*Ff)[lane];
                    uint2 u1 = reinterpret_cast<const uint2*>(g_xb + e1.x*Ff)[lane];
                    uint2 u2 = reinterpret_cast<const uint2*>(g_xb + e2.x*Ff)[lane];
                    uint2 u3 = reinterpret_cast<const uint2*>(g_xb + e3.x*Ff)[lane];
                    float w0 = __uint_as_float(e0.y), w1 = __uint_as_float(e1.y);
                    float w2 = __uint_as_float(e2.y), w3 = __uint_as_float(e3.y);
                    float2 p0 = __bfloat1622float2(*reinterpret_cast<__nv_bfloat162*>(&u0.x));
                    float2 q0 = __bfloat1622float2(*reinterpret_cast<__nv_bfloat162*>(&u0.y));
                    float2 p1 = __bfloat1622float2(*reinterpret_cast<__nv_bfloat162*>(&u1.x));
                    float2 q1 = __bfloat1622float2(*reinterpret_cast<__nv_bfloat162*>(&u1.y));
                    float2 p2 = __bfloat1622float2(*reinterpret_cast<__nv_bfloat162*>(&u2.x));
                    float2 q2 = __bfloat1622float2(*reinterpret_cast<__nv_bfloat162*>(&u2.y));
                    float2 p3 = __bfloat1622float2(*reinterpret_cast<__nv_bfloat162*>(&u3.x));
                    float2 q3 = __bfloat1622float2(*reinterpret_cast<__nv_bfloat162*>(&u3.y));
                    a.x += w0*p0.x + w1*p1.x + w2*p2.x + w3*p3.x;
                    a.y += w0*p0.y + w1*p1.y + w2*p2.y + w3*p3.y;
                    a.z += w0*q0.x + w1*q1.x + w2*q2.x + w3*q3.x;
                    a.w += w0*q0.y + w1*q1.y + w2*q2.y + w3*q3.y;
                }
                for (; k < cnt_c; k++) {
                    uint2 e0 = ep[k];
                    uint2 u0 = reinterpret_cast<const uint2*>(g_xb + e0.x*Ff)[lane];
                    float w0 = __uint_as_float(e0.y);
                    float2 p0 = __bfloat1622float2(*reinterpret_cast<__nv_bfloat162*>(&u0.x));
                    float2 q0 = __bfloat1622float2(*reinterpret_cast<__nv_bfloat162*>(&u0.y));
                    a.x += w0*p0.x;  a.y += w0*p0.y;
                    a.z += w0*q0.x;  a.w += w0*q0.y;
                }
            }
            a.x *= nd_c; a.y *= nd_c; a.z *= nd_c; a.w *= nd_c;
            __nv_bfloat162 o0 = __floats2bfloat162_rn(a.x, a.y);
            __nv_bfloat162 o1 = __floats2bfloat162_rn(a.z, a.w);
            uint2 ou;
            ou.x = *reinterpret_cast<unsigned*>(&o0);
            ou.y = *reinterpret_cast<unsigned*>(&o1);
            reinterpret_cast<uint2*>(Ag + rowi*Ff)[lane] = ou;
            rowi = rowi_n; off_c = off_n; cnt_c = cnt_n; nd_c = nd_n;
        }
        __syncthreads();                      // Ag complete

        // ---- MMA: C += Ag @ (Whi_r + Wlo_r); B direct from global ----
        const __nv_bfloat16* Wh = g_Whi + r*Ff*Ff;
        const __nv_bfloat16* Wl = g_Wlo + r*Ff*Ff;
        #pragma unroll
        for (int kf = 0; kf < Ff; kf += 16) {
            #pragma unroll
            for (int i = 0; i < 2; i++) {
                wmma::fragment<wmma::matrix_a, 16, 16, 16, __nv_bfloat16, wmma::row_major> af;
                wmma::load_matrix_sync(af, Ag + (wm*32 + i*16)*Ff + kf, Ff);
                #pragma unroll
                for (int j = 0; j < 2; j++) {
                    wmma::fragment<wmma::matrix_b, 16, 16, 16, __nv_bfloat16, wmma::row_major> bf;
                    wmma::load_matrix_sync(bf, Wh + kf*Ff + wn*32 + j*16, Ff);
                    wmma::mma_sync(acc[i][j], af, bf, acc[i][j]);
                    wmma::load_matrix_sync(bf, Wl + kf*Ff + wn*32 + j*16, Ff);
                    wmma::mma_sync(acc[i][j], af, bf, acc[i][j]);
                }
            }
        }
        __syncthreads();                      // MMA reads done before Ag overwrite
    }

    // ---- fused epilogue: relu + bias, weighted reduction into g_M ----
    float* Cs = reinterpret_cast<float*>(sm);                // 64x128 f32 (32KB)
    float* wc = reinterpret_cast<float*>(sm + 32768);        // [6][128]  (3KB)
    float* Mp = reinterpret_cast<float*>(sm + 35840);        // [4][6][128] (12KB)

    int col = t & 127;
    int q   = t >> 7;                        // thread quarter 0..3
    float b1s = g_b1sum[col];
    float ma[Rr];
    #pragma unroll
    for (int r = 0; r < Rr; r++) ma[r] = 0.f;

    for (int u = t; u < Rr*MBLK; u += NTHR) {
        int r = u >> 7, row = u & 127;
        int gr = rowbase + row;
        wc[u] = (gr < Nn) ? g_wc[r*Nn + gr] : 0.f;
    }

    #pragma unroll
    for (int p = 0; p < 2; p++) {
        __syncthreads();                     // smem free / prev pass consumed
        if ((wm >> 1) == p) {                // warps owning rows [p*64, p*64+64)
            #pragma unroll
            for (int i = 0; i < 2; i++)
                #pragma unroll
                for (int j = 0; j < 2; j++)
                    wmma::store_matrix_sync(Cs + ((wm & 1)*32 + i*16)*128 + wn*32 + j*16,
                                            acc[i][j], 128, wmma::mem_row_major);
        }
        __syncthreads();
        #pragma unroll 4
        for (int rw = 0; rw < 16; rw++) {
            int row64 = q*16 + rw;
            int grow  = p*64 + row64;
            float v = fmaxf(Cs[row64*128 + col] + b1s, 0.f);   // h1 (fp32)
            #pragma unroll
            for (int r = 0; r < Rr; r++)
                ma[r] += wc[r*MBLK + grow] * v;
        }
    }
    __syncthreads();
    #pragma unroll
    for (int r = 0; r < Rr; r++) Mp[(q*Rr + r)*128 + col] = ma[r];
    __syncthreads();
    for (int u = t; u < Rr*Ff; u += NTHR)
        atomicAdd(&g_M[u], Mp[u] + Mp[768 + u] + Mp[1536 + u] + Mp[2304 + u]);
}

// g = (1/N) sum_r M[r] @ W2_r + sum_r b2_r ; out = g @ Wc + bc
__global__ void k_out(const float* __restrict__ W2, const float* __restrict__ b2,
                      const float* __restrict__ Wc, const float* __restrict__ bc,
                      float* __restrict__ out) {
    __shared__ float g[Ff];
    int t = threadIdx.x;
    float acc = 0.f, bb = 0.f;
    for (int r = 0; r < Rr; r++) {
        const float* W2r = W2 + r*Ff*Ff;
        for (int h = 0; h < Ff; h++)
            acc += g_M[r*Ff + h] * W2r[h*Ff + t];
        bb += b2[r*Ff + t];
    }
    g[t] = acc * (1.f / (float)Nn) + bb;
    __syncthreads();
    if (t < 2) {
        float o = bc[t];
        for (int h = 0; h < Ff; h++) o += g[h] * Wc[h*2 + t];
        out[t] = o;
    }
}

// ---------------- launch ------------------------------------------------------
extern "C" void kernel_launch(void* const* d_in, const int* in_sizes, int n_in,
                              void* d_out, int out_size) {
    const float* x    = (const float*)d_in[0];
    const int*   esrc = (const int*)  d_in[1];
    const int*   edst = (const int*)  d_in[2];
    const float* W1   = (const float*)d_in[3];
    const float* b1   = (const float*)d_in[4];
    const float* W2   = (const float*)d_in[5];
    const float* b2   = (const float*)d_in[6];
    const float* Wc   = (const float*)d_in[7];
    const float* bc   = (const float*)d_in[8];
    float* out = (float*)d_out;

    k_init   <<<(Nn*Ff + 255)/256, 256>>>(x, W1, b1);
    k_deg    <<<(RE + 255)/256, 256>>>(esrc, edst);
    k_norm   <<<(NR + 255)/256, 256>>>();
    k_scatter<<<(RE + 255)/256, 256>>>(esrc, edst);
    k_pre    <<<(NR + 255)/256, 256>>>();
    k_fused  <<<NBLKS, NTHR>>>();
    k_out    <<<1, 128>>>(W2, b2, Wc, bc, out);
}